// round 16
// baseline (speedup 1.0000x reference)
#include <cuda_runtime.h>

#define NW      10000
#define MAXLEN  14
#define QCOUNT  32     // BSZ*SEQ
#define TPB     64
#define SORT_B  256
#define NSB     ((NW + SORT_B - 1) / SORT_B)   // 40 blocks, co-resident

// Scratch (no allocation allowed)
__device__ int   g_wlen_s[NW];
__device__ int   g_orig_s[NW];
__device__ uint4 g_packed[NW];
__device__ int   g_qorder[QCOUNT];
__device__ int   g_cnt[NSB][16];
__device__ int   g_arrive;        // zero-init; reset by last block each run
__device__ int   g_finish;

// -------------------------------------------------------------------------
// Counting-sort, DESCENDING length, two-phase with inter-block spin barrier:
// phase A: each block histograms ONLY its own 256 words (atomic return =
// within-block rank), publishes counts; phase B (after all 40 arrive): each
// block sums bins over blocks (L2), prefixes, scatters + packs.
// 40 blocks <= 148 SMs -> all co-resident -> spin is deadlock-free.
// Counters are reset by the last finishing block => graph-replay safe.
// -------------------------------------------------------------------------
__global__ void __launch_bounds__(SORT_B)
fused_sort_kernel(const int* __restrict__ words, const int* __restrict__ wl,
                  const int* __restrict__ x) {
    __shared__ int h_loc[16];
    __shared__ int s_tot[16];
    __shared__ int s_bef[16];
    __shared__ int base[16];

    const int t  = threadIdx.x;
    const int bx = blockIdx.x;
    const int w  = bx * SORT_B + t;

    if (t < 16) h_loc[t] = 0;
    __syncthreads();

    // Phase A: own-words histogram; atomic return value = within-block rank
    int len = 0, rank = 0;
    if (w < NW) {
        len  = wl[w];
        rank = atomicAdd(&h_loc[len], 1);
    }
    __syncthreads();
    if (t < 16) g_cnt[bx][t] = h_loc[t];
    __threadfence();
    __syncthreads();
    if (t == 0) {
        atomicAdd(&g_arrive, 1);
        while (atomicAdd(&g_arrive, 0) < NSB) { }   // spin until all published
    }
    __syncthreads();

    // Phase B: totals + before-block counts from L2 (bypass L1 via __ldcg)
    if (t >= 1 && t <= MAXLEN) {
        int tot = 0, bef = 0;
        #pragma unroll 4
        for (int b = 0; b < NSB; ++b) {
            int c = __ldcg(&g_cnt[b][t]);
            tot += c;
            if (b < bx) bef += c;
        }
        s_tot[t] = tot;
        s_bef[t] = bef;
    }
    __syncthreads();
    if (t == 0) {
        int acc = 0;
        for (int l = MAXLEN; l >= 1; --l) { base[l] = acc; acc += s_tot[l]; }  // descending
    }
    __syncthreads();

    if (w < NW) {
        int pos = base[len] + s_bef[len] + rank;
        g_wlen_s[pos] = len;
        g_orig_s[pos] = w;
        unsigned int p[4] = {0u, 0u, 0u, 0u};
        #pragma unroll
        for (int c = 0; c < MAXLEN; ++c) {
            unsigned int ch = (unsigned int)words[w * MAXLEN + c] & 0xFFu;
            p[c >> 2] |= ch << ((c & 3) * 8);
        }
        g_packed[pos] = make_uint4(p[0], p[1], p[2], p[3]);
    }

    // Block 0: q-order by descending swl — parallel stable rank.
    if (bx == 0) {
        __shared__ int s_swl[QCOUNT];
        if (t < QCOUNT) {
            int sw = 0, best = x[t * (MAXLEN + 1)];
            #pragma unroll
            for (int c = 1; c <= MAXLEN; ++c) {
                int v = x[t * (MAXLEN + 1) + c];
                if (v > best) { best = v; sw = c; }
            }
            s_swl[t] = sw;
        }
        __syncthreads();
        if (t < QCOUNT) {
            int mine = s_swl[t];
            int r = 0;
            #pragma unroll
            for (int j = 0; j < QCOUNT; ++j) {
                int sj = s_swl[j];
                r += (sj > mine) || (sj == mine && j < t);
            }
            g_qorder[r] = t;
        }
    }

    // Reset counters for the next graph replay (last block to finish)
    __syncthreads();
    if (t == 0) {
        if (atomicAdd(&g_finish, 1) == NSB - 1) {
            atomicExch(&g_arrive, 0);
            atomicExch(&g_finish, 0);
        }
    }
}

// -------------------------------------------------------------------------
// Main kernel: EXACT R15 structure (proven; 64 regs, occ 43.9%, issue 83%).
// One thread per (query, sorted word); 14x14 per-thread byte matrix in smem
// serves only the transposition gather. q = g_qorder[blockIdx.y].
// -------------------------------------------------------------------------
__global__ void __launch_bounds__(TPB)
dl_kernel(const int* __restrict__ x, float* __restrict__ out) {
    __shared__ unsigned char d_s[14 * 14 * TPB];   // 196 B per thread
    __shared__ int s_x[MAXLEN + 1];

    const int tid  = threadIdx.x;
    const int q    = g_qorder[blockIdx.y];
    const int slot = blockIdx.x * TPB + tid;

    if (tid < MAXLEN + 1) s_x[tid] = x[q * (MAXLEN + 1) + tid];
    __syncthreads();

    // swl = first-argmax over the 15 chars (jnp.argmax semantics)
    int swl = 0, best = s_x[0];
    #pragma unroll
    for (int t = 1; t <= MAXLEN; ++t) {
        int v = s_x[t];
        if (v > best) { best = v; swl = t; }
    }

    int wlen = 0, orig = 0;
    unsigned int pw0 = 0, pw1 = 0, pw2 = 0, pw3 = 0;
    if (slot < NW) {
        wlen = g_wlen_s[slot];
        orig = g_orig_s[slot];
        uint4 p = g_packed[slot];
        pw0 = p.x; pw1 = p.y; pw2 = p.z; pw3 = p.w;
    }

    int wc[MAXLEN];
    #pragma unroll
    for (int c = 0; c < MAXLEN; ++c) {
        unsigned int r = (c < 4) ? pw0 : (c < 8) ? pw1 : (c < 12) ? pw2 : pw3;
        wc[c] = (int)((r >> ((c & 3) * 8)) & 0xFFu);
    }
    int kreg[MAXLEN];
    #pragma unroll
    for (int c = 0; c < MAXLEN; ++c) kreg[c] = 0;

    const int maxd = swl + wlen;
    unsigned char* bp = d_s + tid;

    // Init gather-reachable boundary cells (rows 0..swl-1, cols 0..wlen-1):
    //   d[0][l] = maxd ; d[1][0] = maxd ; d[1][l>=1] = l-1
    //   d[k][0] = maxd, d[k][1] = k-1   for k = 2..swl-1
    for (int l = 0; l < wlen; ++l) {
        bp[(0 * 14 + l) * TPB] = (unsigned char)maxd;
        bp[(1 * 14 + l) * TPB] = (unsigned char)(l == 0 ? maxd : l - 1);
    }
    for (int k = 2; k < swl; ++k) {
        bp[(k * 14 + 0) * TPB] = (unsigned char)maxd;
        bp[(k * 14 + 1) * TPB] = (unsigned char)(k - 1);
    }

    // prev[j] = d[i][j]; row 1: d[1][j] = j-1
    int prev[16];
    #pragma unroll
    for (int j = 1; j <= 15; ++j) prev[j] = j - 1;

    int res = wlen;                        // swl == 0: d[1][wlen+1] = wlen
    const int rlimit = swl - 2;            // last row whose store matters
    const int climit = wlen - 2;           // last col whose store matters
    for (int i = 1; i <= swl; ++i) {       // uniform per block
        const int xc  = s_x[i - 1];
        const int im1 = i - 1;
        int db   = 0;
        int left = i;                      // d[i+1][1] = i
        unsigned char* rowp = bp + ((i + 1) * 14) * TPB;
        const bool rkeep = (i <= rlimit);
        #pragma unroll
        for (int j = 1; j <= 15; ++j) {
            if (j > wlen || j == 15) { prev[j] = left; break; }   // d[i+1][j]
            const bool p  = (xc == wc[j - 1]);
            const int up   = prev[j + 1];
            const int diag = prev[j];
            const int k = kreg[j - 1];
            const int l = db;
            const int dtr   = (int)bp[(k * 14 + l) * TPB];        // LDS.U8
            const int trans = dtr + (im1 + j - k - l);
            int m = min(up, left) + 1;
            m = min(m, diag + (p ? 0 : 1));
            m = min(m, trans);
            if (p) { db = j; kreg[j - 1] = i; }
            if (rkeep && j <= climit)
                rowp[(j + 1) * TPB] = (unsigned char)m;           // d[i+1][j+1]
            prev[j] = left;
            left = m;
        }
        res = left;                        // d[i+1][wlen+1]
    }

    if (slot < NW) out[q * NW + orig] = (float)res;
}

// -------------------------------------------------------------------------
extern "C" void kernel_launch(void* const* d_in, const int* in_sizes, int n_in,
                              void* d_out, int out_size) {
    const int* x     = (const int*)d_in[0];   // (2,16,15) int32
    const int* words = (const int*)d_in[1];   // (10000,14) int32
    const int* wl    = (const int*)d_in[2];   // (10000,) int32
    float* out = (float*)d_out;               // (2,16,10000) float32

    fused_sort_kernel<<<NSB, SORT_B>>>(words, wl, x);
    dim3 grid((NW + TPB - 1) / TPB, QCOUNT);
    dl_kernel<<<grid, TPB>>>(x, out);
}